// round 4
// baseline (speedup 1.0000x reference)
#include <cuda_runtime.h>
#include <cuda_fp16.h>
#include <mma.h>
#include <math.h>

using namespace nvcuda;

#define N_NODES 50000
#define NPAD 50048          // 782 * 64
#define N_EDGES 400000
#define N_GRAPHS 512
#define NF 64
#define EF 32
#define AIF 92
#define AIFP 96             // padded K for wmma
#define FCF 128
#define NLAYERS 3
#define TBINS 16384
#define TROWS 16385
#define BN_EPS 1e-5f

// ---------------- static scratch ----------------
__device__ __align__(16) float   d_h[NPAD * NF];               // fp32 node features
__device__ __align__(16) __half  d_hh[NPAD * NF];              // fp16 copy for HMMA
__device__ __align__(16) float   d_agg[NPAD * NF];
__device__ __align__(16) __half2 d_ABp[NPAD * 128];            // packed (i,u): [0..63]=A, [64..127]=B
__device__ __align__(16) __half2 d_pre[N_EDGES * 64];          // 102 MB, CSR-ordered pre-activations
__device__ __align__(16) __half2 d_tab[NLAYERS * TROWS * 64];  // RBF@W table (nearest bin)
__device__ __align__(16) __half  d_wbigh[NLAYERS * 64 * 256];  // fp16 weights, cols interleaved (even=i odd=u)
__device__ __align__(16) __half  d_atomh[NPAD * AIFP];         // fp16 atom features, K padded
__device__ __align__(16) __half  d_wembh[AIFP * NF];
__device__ __align__(16) float   d_E[TROWS * EF];
__device__ int   d_counts[N_NODES];
__device__ int   d_rowstart[N_NODES + 1];
__device__ int   d_cursor[N_NODES];
__device__ int   d_bsum[128];
__device__ int   d_boff[128];
__device__ int   d_csr_eid[N_EDGES];
__device__ int   d_csr_src[N_EDGES];
__device__ int   d_csr_dst[N_EDGES];
__device__ float d_csr_bond[N_EDGES];
__device__ float d_estat[256];    // [s1_i|s2_i|s1_u|s2_u] x 64
__device__ float d_escale[128];
__device__ float d_eshift[128];
__device__ float d_nstat[128];
__device__ float d_nscale[64];
__device__ float d_nshift[64];

// ---------------- fast math ----------------
__device__ __forceinline__ float fsig(float x) {
    return __fdividef(1.f, 1.f + __expf(-x));
}
__device__ __forceinline__ float fsp(float x) {
    return fmaxf(x, 0.f) + __logf(1.f + __expf(-fabsf(x)));
}

// ---------------- prep: pack fp16 weights (interleaved), zero state ----------------
__global__ void k_wbig(const float* __restrict__ Wi, const float* __restrict__ Wu) {
    int tid = threadIdx.x;
    int idx = blockIdx.x * blockDim.x + tid;
    if (blockIdx.x == 0) {
        if (tid < 256) d_estat[tid] = 0.f;
        else if (tid < 384) d_nstat[tid - 256] = 0.f;
    }
    for (int i = idx; i < N_NODES; i += gridDim.x * blockDim.x) d_counts[i] = 0;
    if (idx >= NLAYERS * 64 * 256) return;
    int l = idx / 16384;
    int r = idx - l * 16384;
    int k = r >> 8;
    int c = r & 255;
    float v;
    if (c < 128) {
        int f = c >> 1;
        int base = (l * 160 + k) * 64 + f;
        v = (c & 1) ? Wu[base] : Wi[base];
    } else {
        int f = (c - 128) >> 1;
        int base = (l * 160 + 64 + k) * 64 + f;
        v = (c & 1) ? Wu[base] : Wi[base];
    }
    d_wbigh[idx] = __float2half(v);
}

// ---------------- RBF basis + table ----------------
__global__ void k_etab() {
    int idx = blockIdx.x * blockDim.x + threadIdx.x;
    if (idx >= TROWS * EF) return;
    int t = idx >> 5, k = idx & 31;
    float d = (float)t * (8.0f / (float)TBINS);
    float ck = (float)k * (8.0f / 31.0f);
    float diff = d - ck;
    d_E[idx] = expf(-3.875f * diff * diff);
}

__global__ void k_table(const float* __restrict__ Wi, const float* __restrict__ Wu) {
    int b = blockIdx.x;
    int l = b / TROWS;
    int t = b - l * TROWS;
    int f = threadIdx.x;   // 0..63
    __shared__ float er[EF];
    if (f < EF) er[f] = d_E[t * EF + f];
    __syncthreads();
    const float* wi = Wi + (l * 160 + 128) * 64 + f;
    const float* wu = Wu + (l * 160 + 128) * 64 + f;
    float ai = 0.f, au = 0.f;
#pragma unroll
    for (int k = 0; k < EF; k++) {
        ai = fmaf(er[k], wi[k * 64], ai);
        au = fmaf(er[k], wu[k * 64], au);
    }
    d_tab[(l * TROWS + t) * 64 + f] = __floats2half2_rn(ai, au);
}

// ---------------- fp16 conversions for embed HMMA ----------------
__global__ void k_convatom(const float* __restrict__ atom) {
    int idx = blockIdx.x * blockDim.x + threadIdx.x;
    if (idx >= NPAD * AIFP) return;
    int row = idx / AIFP, col = idx - row * AIFP;
    float v = (row < N_NODES && col < AIF) ? atom[row * AIF + col] : 0.f;
    d_atomh[idx] = __float2half(v);
}

__global__ void k_convw(const float* __restrict__ W) {
    int idx = blockIdx.x * blockDim.x + threadIdx.x;
    if (idx >= AIFP * NF) return;
    int k = idx >> 6, c = idx & 63;
    d_wembh[idx] = __float2half(k < AIF ? W[k * 64 + c] : 0.f);
}

// ---------------- CSR build ----------------
__global__ void k_count(const int* __restrict__ dst) {
    int e = blockIdx.x * blockDim.x + threadIdx.x;
    if (e < N_EDGES) atomicAdd(&d_counts[dst[e]], 1);
}

__global__ void k_scan1() {
    int b = blockIdx.x, tid = threadIdx.x;
    int i = b * 512 + tid;
    int v = (i < N_NODES) ? d_counts[i] : 0;
    __shared__ int s[512];
    s[tid] = v;
    __syncthreads();
    for (int o = 1; o < 512; o <<= 1) {
        int t = (tid >= o) ? s[tid - o] : 0;
        __syncthreads();
        s[tid] += t;
        __syncthreads();
    }
    if (i < N_NODES) d_rowstart[i] = s[tid] - v;
    if (tid == 511) d_bsum[b] = s[511];
}

__global__ void k_scan2(int nblk) {
    int tid = threadIdx.x;   // 128
    int v = (tid < nblk) ? d_bsum[tid] : 0;
    __shared__ int s[128];
    s[tid] = v;
    __syncthreads();
    for (int o = 1; o < 128; o <<= 1) {
        int t = (tid >= o) ? s[tid - o] : 0;
        __syncthreads();
        s[tid] += t;
        __syncthreads();
    }
    d_boff[tid] = s[tid] - v;
}

__global__ void k_scan3() {
    int i = blockIdx.x * blockDim.x + threadIdx.x;
    if (i >= N_NODES) return;
    int rs = d_rowstart[i] + d_boff[i >> 9];
    d_rowstart[i] = rs;
    d_cursor[i] = rs;
    if (i == 0) d_rowstart[N_NODES] = N_EDGES;
}

__global__ void k_fill(const int* __restrict__ dst) {
    int e = blockIdx.x * blockDim.x + threadIdx.x;
    if (e >= N_EDGES) return;
    int pos = atomicAdd(&d_cursor[dst[e]], 1);
    d_csr_eid[pos] = e;
}

__global__ void k_sort() {
    int n = blockIdx.x * blockDim.x + threadIdx.x;
    if (n >= N_NODES) return;
    int s = d_rowstart[n], e = d_rowstart[n + 1];
    for (int i = s + 1; i < e; i++) {
        int v = d_csr_eid[i];
        int j = i - 1;
        while (j >= s && d_csr_eid[j] > v) {
            d_csr_eid[j + 1] = d_csr_eid[j];
            j--;
        }
        d_csr_eid[j + 1] = v;
    }
}

__global__ void k_csrgather(const int* __restrict__ src, const int* __restrict__ dst,
                            const float* __restrict__ bond) {
    int i = blockIdx.x * blockDim.x + threadIdx.x;
    if (i >= N_EDGES) return;
    int e = d_csr_eid[i];
    d_csr_src[i] = src[e];
    d_csr_dst[i] = dst[e];
    d_csr_bond[i] = bond[e];
}

// ---------------- embed GEMM via HMMA: h = atomh[NPAD,96] @ wembh[96,64] + b ----------------
__global__ __launch_bounds__(256) void k_gemm_embh(const float* __restrict__ bias) {
    int m0 = blockIdx.x * 128;
    int wid = threadIdx.x >> 5;
    int lane = threadIdx.x & 31;
    int mw = wid & 3;        // 4 m-warps * 32 rows
    int nw = wid >> 2;       // 2 n-warps * 32 cols

    wmma::fragment<wmma::accumulator, 16, 16, 16, float> acc[2][2];
#pragma unroll
    for (int mi = 0; mi < 2; mi++)
#pragma unroll
        for (int nj = 0; nj < 2; nj++) wmma::fill_fragment(acc[mi][nj], 0.f);

#pragma unroll
    for (int kk = 0; kk < 6; kk++) {
        wmma::fragment<wmma::matrix_a, 16, 16, 16, __half, wmma::row_major> af[2];
        wmma::fragment<wmma::matrix_b, 16, 16, 16, __half, wmma::row_major> bf[2];
#pragma unroll
        for (int mi = 0; mi < 2; mi++)
            wmma::load_matrix_sync(af[mi], d_atomh + (m0 + mw * 32 + mi * 16) * AIFP + kk * 16, AIFP);
#pragma unroll
        for (int nj = 0; nj < 2; nj++)
            wmma::load_matrix_sync(bf[nj], d_wembh + (kk * 16) * 64 + nw * 32 + nj * 16, 64);
#pragma unroll
        for (int mi = 0; mi < 2; mi++)
#pragma unroll
            for (int nj = 0; nj < 2; nj++)
                wmma::mma_sync(acc[mi][nj], af[mi], bf[nj], acc[mi][nj]);
    }

    __shared__ float patch[8][256];
    float* p = patch[wid];
#pragma unroll
    for (int mi = 0; mi < 2; mi++)
#pragma unroll
        for (int nj = 0; nj < 2; nj++) {
            wmma::store_matrix_sync(p, acc[mi][nj], 16, wmma::mem_row_major);
            __syncwarp();
            int row0 = m0 + mw * 32 + mi * 16;
            int col0 = nw * 32 + nj * 16;
#pragma unroll
            for (int j = 0; j < 8; j++) {
                int q = lane + 32 * j;        // 0..255
                int r = q >> 4, c = q & 15;
                float v = p[r * 16 + c] + bias[col0 + c];
                int o = (row0 + r) * 64 + col0 + c;
                d_h[o] = v;
                d_hh[o] = __float2half(v);
            }
            __syncwarp();
        }
}

// ---------------- layer GEMM via HMMA: ABp = hh[NPAD,64] @ wbigh[l][64,256] ----------------
__global__ __launch_bounds__(256) void k_gemmAB(int layer) {
    const __half* A = d_hh;
    const __half* B = d_wbigh + layer * 64 * 256;
    int m0 = blockIdx.x * 64;
    int wid = threadIdx.x >> 5;
    int lane = threadIdx.x & 31;
    int mw = wid & 1;
    int nw = wid >> 1;

    wmma::fragment<wmma::accumulator, 16, 16, 16, float> acc[2][4];
#pragma unroll
    for (int mi = 0; mi < 2; mi++)
#pragma unroll
        for (int nj = 0; nj < 4; nj++) wmma::fill_fragment(acc[mi][nj], 0.f);

#pragma unroll
    for (int kk = 0; kk < 4; kk++) {
        wmma::fragment<wmma::matrix_a, 16, 16, 16, __half, wmma::row_major> af[2];
        wmma::fragment<wmma::matrix_b, 16, 16, 16, __half, wmma::row_major> bf[4];
#pragma unroll
        for (int mi = 0; mi < 2; mi++)
            wmma::load_matrix_sync(af[mi], A + (m0 + mw * 32 + mi * 16) * 64 + kk * 16, 64);
#pragma unroll
        for (int nj = 0; nj < 4; nj++)
            wmma::load_matrix_sync(bf[nj], B + (kk * 16) * 256 + nw * 64 + nj * 16, 256);
#pragma unroll
        for (int mi = 0; mi < 2; mi++)
#pragma unroll
            for (int nj = 0; nj < 4; nj++)
                wmma::mma_sync(acc[mi][nj], af[mi], bf[nj], acc[mi][nj]);
    }

    __shared__ float patch[8][256];
    float* p = patch[wid];
#pragma unroll
    for (int mi = 0; mi < 2; mi++)
#pragma unroll
        for (int nj = 0; nj < 4; nj++) {
            wmma::store_matrix_sync(p, acc[mi][nj], 16, wmma::mem_row_major);
            __syncwarp();
            int row0 = m0 + mw * 32 + mi * 16;
            int pairbase = nw * 32 + nj * 8;
#pragma unroll
            for (int j = 0; j < 4; j++) {
                int q = lane * 4 + j;
                int r = q >> 3, pp = q & 7;
                d_ABp[(row0 + r) * 128 + pairbase + pp] =
                    __floats2half2_rn(p[r * 16 + 2 * pp], p[r * 16 + 2 * pp + 1]);
            }
            __syncwarp();
        }
}

// ---------------- P-pass: edge-centric gather + pre store + edge BN stats ----------------
__global__ __launch_bounds__(256) void k_pre(int layer) {
    int tid = threadIdx.x;
    int f = tid & 63, g = tid >> 6;
    const __half2* Tb = d_tab + layer * TROWS * 64;
    float s1i = 0.f, s2i = 0.f, s1u = 0.f, s2u = 0.f;
    for (int i = blockIdx.x * 4 + g; i < N_EDGES; i += gridDim.x * 4) {
        int sn = d_csr_src[i];
        int dn = d_csr_dst[i];
        float bl = d_csr_bond[i];
        float2 a = __half22float2(d_ABp[sn * 128 + f]);
        float2 b = __half22float2(d_ABp[dn * 128 + 64 + f]);
        int t = __float2int_rn(bl * ((float)TBINS / 8.0f));
        float2 u = __half22float2(Tb[t * 64 + f]);
        __half2 ph = __floats2half2_rn(a.x + b.x + u.x, a.y + b.y + u.y);
        d_pre[i * 64 + f] = ph;
        float2 pq = __half22float2(ph);   // stats on the stored (rounded) values
        s1i += pq.x; s2i = fmaf(pq.x, pq.x, s2i);
        s1u += pq.y; s2u = fmaf(pq.y, pq.y, s2u);
    }
    __shared__ float red[256];
    red[tid] = s1i; __syncthreads();
    if (tid < 64) atomicAdd(&d_estat[f], red[f] + red[f + 64] + red[f + 128] + red[f + 192]);
    __syncthreads(); red[tid] = s2i; __syncthreads();
    if (tid < 64) atomicAdd(&d_estat[64 + f], red[f] + red[f + 64] + red[f + 128] + red[f + 192]);
    __syncthreads(); red[tid] = s1u; __syncthreads();
    if (tid < 64) atomicAdd(&d_estat[128 + f], red[f] + red[f + 64] + red[f + 128] + red[f + 192]);
    __syncthreads(); red[tid] = s2u; __syncthreads();
    if (tid < 64) atomicAdd(&d_estat[192 + f], red[f] + red[f + 64] + red[f + 128] + red[f + 192]);
}

__global__ void k_ebn(const float* __restrict__ gi, const float* __restrict__ bti,
                      const float* __restrict__ gu, const float* __restrict__ btu,
                      int layer) {
    int c = threadIdx.x;  // 0..127
    float mean, var, g, bt;
    if (c < 64) {
        mean = d_estat[c] / (float)N_EDGES;
        var  = d_estat[64 + c] / (float)N_EDGES - mean * mean;
        g = gi[layer * 64 + c]; bt = bti[layer * 64 + c];
    } else {
        int f = c - 64;
        mean = d_estat[128 + f] / (float)N_EDGES;
        var  = d_estat[192 + f] / (float)N_EDGES - mean * mean;
        g = gu[layer * 64 + f]; bt = btu[layer * 64 + f];
    }
    float sc = g * rsqrtf(var + BN_EPS);
    d_escale[c] = sc;
    d_eshift[c] = bt - mean * sc;
    d_estat[c] = 0.f;
    d_estat[128 + c] = 0.f;
}

// ---------------- apply: streaming read of pre, activations, register agg, node stats ----
__global__ __launch_bounds__(256) void k_apply() {
    __shared__ float sci[64], shi[64], scu[64], shu[64];
    int tid = threadIdx.x;
    if (tid < 64) {
        sci[tid] = d_escale[tid];      shi[tid] = d_eshift[tid];
        scu[tid] = d_escale[64 + tid]; shu[tid] = d_eshift[64 + tid];
    }
    __syncthreads();
    int f = tid & 63, g = tid >> 6;
    float ci = sci[f], hi = shi[f], cu = scu[f], hu = shu[f];
    float s1 = 0.f, s2 = 0.f;
    for (int n = blockIdx.x * 4 + g; n < N_NODES; n += gridDim.x * 4) {
        int a0 = d_rowstart[n], a1 = d_rowstart[n + 1];
        float acc = 0.f;
        for (int i = a0; i < a1; i++) {
            float2 p = __half22float2(d_pre[i * 64 + f]);
            float gate = fsig(fmaf(p.x, ci, hi));
            float upd = fsp(fmaf(p.y, cu, hu));
            acc = fmaf(gate, upd, acc);
        }
        d_agg[n * 64 + f] = acc;
        s1 += acc;
        s2 = fmaf(acc, acc, s2);
    }
    __shared__ float red[256];
    red[tid] = s1; __syncthreads();
    if (tid < 64) atomicAdd(&d_nstat[f], red[f] + red[f + 64] + red[f + 128] + red[f + 192]);
    __syncthreads(); red[tid] = s2; __syncthreads();
    if (tid < 64) atomicAdd(&d_nstat[64 + f], red[f] + red[f + 64] + red[f + 128] + red[f + 192]);
}

__global__ void k_nbn(const float* __restrict__ g_bn, const float* __restrict__ b_bn, int layer) {
    int f = threadIdx.x;  // 0..63
    float mean = d_nstat[f] / (float)N_NODES;
    float var = d_nstat[64 + f] / (float)N_NODES - mean * mean;
    float sc = g_bn[layer * 64 + f] * rsqrtf(var + BN_EPS);
    d_nscale[f] = sc;
    d_nshift[f] = b_bn[layer * 64 + f] - mean * sc;
    d_nstat[f] = 0.f;
    d_nstat[64 + f] = 0.f;
}

__global__ __launch_bounds__(256) void k_N2() {
    __shared__ float sc[64], sh[64];
    int tid = threadIdx.x;
    if (tid < 64) { sc[tid] = d_nscale[tid]; sh[tid] = d_nshift[tid]; }
    __syncthreads();
    int total = N_NODES * NF;
    for (int i = blockIdx.x * 256 + tid; i < total; i += gridDim.x * 256) {
        int f = i & 63;
        float a = fmaf(d_agg[i], sc[f], sh[f]);
        float v = fsp(d_h[i] + a);
        d_h[i] = v;
        d_hh[i] = __float2half(v);
    }
}

// ---------------- final: mean pool per graph + MLP head ----------------
__device__ __forceinline__ int lbound(const int* a, int n, int v) {
    int lo = 0, hi = n;
    while (lo < hi) {
        int mid = (lo + hi) >> 1;
        if (a[mid] < v) lo = mid + 1; else hi = mid;
    }
    return lo;
}

__global__ __launch_bounds__(128) void k_final(const int* __restrict__ gids,
                                               const float* __restrict__ Wfc,
                                               const float* __restrict__ bfc,
                                               const float* __restrict__ Wout,
                                               const float* __restrict__ bout,
                                               float* __restrict__ out) {
    int g = blockIdx.x;
    int tid = threadIdx.x;
    __shared__ int bounds[2];
    __shared__ float f1s[64];
    __shared__ float red[128];
    if (tid == 0) {
        bounds[0] = lbound(gids, N_NODES, g);
        bounds[1] = lbound(gids, N_NODES, g + 1);
    }
    __syncthreads();
    int lo = bounds[0], hi = bounds[1];
    int f = tid & 63, half = tid >> 6;
    float s = 0.f;
    for (int n = lo + half; n < hi; n += 2) s += d_h[n * 64 + f];
    red[tid] = s;
    __syncthreads();
    if (tid < 64) {
        float tot = red[tid] + red[tid + 64];
        float cnt = (float)max(hi - lo, 1);
        f1s[tid] = fsp(tot / cnt);
    }
    __syncthreads();
    float acc = bfc[tid];
#pragma unroll
    for (int k = 0; k < 64; k++) acc = fmaf(f1s[k], Wfc[k * FCF + tid], acc);
    float v = fsp(fsp(acc)) * Wout[tid];
    red[tid] = v;
    __syncthreads();
    for (int st = 64; st > 0; st >>= 1) {
        if (tid < st) red[tid] += red[tid + st];
        __syncthreads();
    }
    if (tid == 0) out[g] = red[0] + bout[0];
}

// ---------------- launch ----------------
extern "C" void kernel_launch(void* const* d_in, const int* in_sizes, int n_in,
                              void* d_out, int out_size) {
    const float* atom  = (const float*)d_in[0];
    const float* bond  = (const float*)d_in[1];
    const int*   src   = (const int*)d_in[2];
    const int*   dst   = (const int*)d_in[3];
    const int*   gids  = (const int*)d_in[4];
    const float* W_emb = (const float*)d_in[5];
    const float* b_emb = (const float*)d_in[6];
    const float* Wi    = (const float*)d_in[7];
    // d_in[8] = bi  — cancels inside training-mode BatchNorm
    const float* gi    = (const float*)d_in[9];
    const float* bti   = (const float*)d_in[10];
    const float* Wu    = (const float*)d_in[11];
    // d_in[12] = bu — cancels
    const float* gu    = (const float*)d_in[13];
    const float* btu   = (const float*)d_in[14];
    const float* g_bn  = (const float*)d_in[15];
    const float* b_bn  = (const float*)d_in[16];
    const float* W_fc  = (const float*)d_in[17];
    const float* b_fc  = (const float*)d_in[18];
    const float* W_out = (const float*)d_in[19];
    const float* b_out = (const float*)d_in[20];
    float* out = (float*)d_out;

    const int EB = (N_EDGES + 255) / 256;   // 1563
    const int NB = (N_NODES + 255) / 256;   // 196
    const int SB = (N_NODES + 511) / 512;   // 98

    k_wbig<<<48, 1024>>>(Wi, Wu);
    k_etab<<<(TROWS * EF + 255) / 256, 256>>>();
    k_table<<<NLAYERS * TROWS, 64>>>(Wi, Wu);
    k_convatom<<<(NPAD * AIFP + 255) / 256, 256>>>(atom);
    k_convw<<<(AIFP * NF + 255) / 256, 256>>>(W_emb);
    k_count<<<EB, 256>>>(dst);
    k_scan1<<<SB, 512>>>();
    k_scan2<<<1, 128>>>(SB);
    k_scan3<<<SB, 512>>>();
    k_fill<<<EB, 256>>>(dst);
    k_sort<<<NB, 256>>>();
    k_csrgather<<<EB, 256>>>(src, dst, bond);

    k_gemm_embh<<<NPAD / 128, 256>>>(b_emb);

    for (int l = 0; l < NLAYERS; l++) {
        k_gemmAB<<<NPAD / 64, 256>>>(l);
        k_pre<<<2048, 256>>>(l);
        k_ebn<<<1, 128>>>(gi, bti, gu, btu, l);
        k_apply<<<1200, 256>>>();
        k_nbn<<<1, 64>>>(g_bn, b_bn, l);
        k_N2<<<2048, 256>>>();
    }

    k_final<<<N_GRAPHS, 128>>>(gids, W_fc, b_fc, W_out, b_out, out);
}

// round 5
// speedup vs baseline: 1.1900x; 1.1900x over previous
#include <cuda_runtime.h>
#include <cuda_fp16.h>
#include <mma.h>
#include <math.h>

using namespace nvcuda;

#define N_NODES 50000
#define NPAD 50048          // 782 * 64
#define N_EDGES 400000
#define N_GRAPHS 512
#define NF 64
#define EF 32
#define AIF 92
#define AIFP 96             // padded K for wmma
#define FCF 128
#define NLAYERS 3
#define TBINS 16384
#define TROWS 16385
#define BN_EPS 1e-5f

// ---------------- static scratch ----------------
__device__ __align__(16) float   d_h[NPAD * NF];
__device__ __align__(16) __half  d_hh[NPAD * NF];
__device__ __align__(16) float   d_agg[NPAD * NF];
__device__ __align__(16) __half2 d_ABp[NPAD * 128];            // packed (i,u): [0..63]=A, [64..127]=B
__device__ __align__(16) __half2 d_tab[NLAYERS * TROWS * 64];  // RBF@W table (nearest bin)
__device__ __align__(16) __half  d_wbigh[NLAYERS * 64 * 256];  // fp16 weights, cols interleaved (even=i odd=u)
__device__ __align__(16) __half  d_atomh[NPAD * AIFP];
__device__ __align__(16) __half  d_wembh[AIFP * NF];
__device__ __align__(16) float   d_E[TROWS * EF];
__device__ int   d_counts[N_NODES];
__device__ int   d_rowstart[N_NODES + 1];
__device__ int   d_cursor[N_NODES];
__device__ int   d_bsum[128];
__device__ int   d_boff[128];
__device__ int   d_csr_eid[N_EDGES];
__device__ int   d_csr_src[N_EDGES];
__device__ int   d_csr_dst[N_EDGES];
__device__ float d_csr_bond[N_EDGES];
__device__ float d_estat[NLAYERS * 256];   // per layer: [s1_i|s2_i|s1_u|s2_u] x 64
__device__ float d_nstat[NLAYERS * 128];   // per layer: [s1|s2] x 64

// ---------------- fast math ----------------
__device__ __forceinline__ float fsig(float x) {
    return __fdividef(1.f, 1.f + __expf(-x));
}
__device__ __forceinline__ float fsp(float x) {
    return fmaxf(x, 0.f) + __logf(1.f + __expf(-fabsf(x)));
}

// ---------------- prep: pack fp16 weights (interleaved), zero stat slabs ----------------
__global__ void k_wbig(const float* __restrict__ Wi, const float* __restrict__ Wu) {
    int tid = threadIdx.x;
    int idx = blockIdx.x * blockDim.x + tid;
    if (blockIdx.x == 0) {
        if (tid < NLAYERS * 256) d_estat[tid] = 0.f;
    } else if (blockIdx.x == 1) {
        if (tid < NLAYERS * 128) d_nstat[tid] = 0.f;
    }
    for (int i = idx; i < N_NODES; i += gridDim.x * blockDim.x) d_counts[i] = 0;
    if (idx >= NLAYERS * 64 * 256) return;
    int l = idx / 16384;
    int r = idx - l * 16384;
    int k = r >> 8;
    int c = r & 255;
    float v;
    if (c < 128) {
        int f = c >> 1;
        int base = (l * 160 + k) * 64 + f;
        v = (c & 1) ? Wu[base] : Wi[base];
    } else {
        int f = (c - 128) >> 1;
        int base = (l * 160 + 64 + k) * 64 + f;
        v = (c & 1) ? Wu[base] : Wi[base];
    }
    d_wbigh[idx] = __float2half(v);
}

// ---------------- RBF basis ----------------
__global__ void k_etab() {
    int idx = blockIdx.x * blockDim.x + threadIdx.x;
    if (idx >= TROWS * EF) return;
    int t = idx >> 5, k = idx & 31;
    float d = (float)t * (8.0f / (float)TBINS);
    float ck = (float)k * (8.0f / 31.0f);
    float diff = d - ck;
    d_E[idx] = expf(-3.875f * diff * diff);
}

// ---------------- table build: block = one layer x 64 t-rows, smem staged ----------------
#define TCH 64
#define TBLK 257   // ceil(TROWS/64)
__global__ __launch_bounds__(256) void k_table(const float* __restrict__ Wi,
                                               const float* __restrict__ Wu) {
    int b = blockIdx.x;
    int l = b / TBLK;
    int t0 = (b - l * TBLK) * TCH;
    int tid = threadIdx.x;
    __shared__ float ws[2][32 * 64];   // 16 KB
    __shared__ float es[TCH * 32];     // 8 KB
    for (int idx = tid; idx < 32 * 64; idx += 256) {
        int k = idx >> 6, f = idx & 63;
        ws[0][idx] = Wi[(l * 160 + 128 + k) * 64 + f];
        ws[1][idx] = Wu[(l * 160 + 128 + k) * 64 + f];
    }
    for (int idx = tid; idx < TCH * 32; idx += 256) {
        int tl = idx >> 5, k = idx & 31;
        int t = t0 + tl;
        es[idx] = (t < TROWS) ? d_E[t * 32 + k] : 0.f;
    }
    __syncthreads();
    for (int o = tid; o < TCH * 64; o += 256) {
        int tl = o >> 6, f = o & 63;
        int t = t0 + tl;
        if (t >= TROWS) continue;
        float ai = 0.f, au = 0.f;
#pragma unroll
        for (int k = 0; k < 32; k++) {
            float e = es[tl * 32 + k];
            ai = fmaf(e, ws[0][k * 64 + f], ai);
            au = fmaf(e, ws[1][k * 64 + f], au);
        }
        d_tab[(l * TROWS + t) * 64 + f] = __floats2half2_rn(ai, au);
    }
}

// ---------------- fp16 conversions for embed HMMA (no integer division) ----------------
__global__ void k_convatom(const float* __restrict__ atom) {
    int col = threadIdx.x;                    // 0..95
    int row = blockIdx.x * 2 + threadIdx.y;   // 2 rows per block
    if (row >= NPAD) return;
    float v = (row < N_NODES && col < AIF) ? atom[row * AIF + col] : 0.f;
    d_atomh[row * AIFP + col] = __float2half(v);
}

__global__ void k_convw(const float* __restrict__ W) {
    int idx = blockIdx.x * blockDim.x + threadIdx.x;
    if (idx >= AIFP * NF) return;
    int k = idx >> 6, c = idx & 63;
    d_wembh[idx] = __float2half(k < AIF ? W[k * 64 + c] : 0.f);
}

// ---------------- CSR build ----------------
__global__ void k_count(const int* __restrict__ dst) {
    int e = blockIdx.x * blockDim.x + threadIdx.x;
    if (e < N_EDGES) atomicAdd(&d_counts[dst[e]], 1);
}

__global__ void k_scan1() {
    int b = blockIdx.x, tid = threadIdx.x;
    int i = b * 512 + tid;
    int v = (i < N_NODES) ? d_counts[i] : 0;
    __shared__ int s[512];
    s[tid] = v;
    __syncthreads();
    for (int o = 1; o < 512; o <<= 1) {
        int t = (tid >= o) ? s[tid - o] : 0;
        __syncthreads();
        s[tid] += t;
        __syncthreads();
    }
    if (i < N_NODES) d_rowstart[i] = s[tid] - v;
    if (tid == 511) d_bsum[b] = s[511];
}

__global__ void k_scan2(int nblk) {
    int tid = threadIdx.x;   // 128
    int v = (tid < nblk) ? d_bsum[tid] : 0;
    __shared__ int s[128];
    s[tid] = v;
    __syncthreads();
    for (int o = 1; o < 128; o <<= 1) {
        int t = (tid >= o) ? s[tid - o] : 0;
        __syncthreads();
        s[tid] += t;
        __syncthreads();
    }
    d_boff[tid] = s[tid] - v;
}

__global__ void k_scan3() {
    int i = blockIdx.x * blockDim.x + threadIdx.x;
    if (i >= N_NODES) return;
    int rs = d_rowstart[i] + d_boff[i >> 9];
    d_rowstart[i] = rs;
    d_cursor[i] = rs;
    if (i == 0) d_rowstart[N_NODES] = N_EDGES;
}

__global__ void k_fill(const int* __restrict__ dst) {
    int e = blockIdx.x * blockDim.x + threadIdx.x;
    if (e >= N_EDGES) return;
    int pos = atomicAdd(&d_cursor[dst[e]], 1);
    d_csr_eid[pos] = e;
}

__global__ void k_sort() {
    int n = blockIdx.x * blockDim.x + threadIdx.x;
    if (n >= N_NODES) return;
    int s = d_rowstart[n], e = d_rowstart[n + 1];
    for (int i = s + 1; i < e; i++) {
        int v = d_csr_eid[i];
        int j = i - 1;
        while (j >= s && d_csr_eid[j] > v) {
            d_csr_eid[j + 1] = d_csr_eid[j];
            j--;
        }
        d_csr_eid[j + 1] = v;
    }
}

__global__ void k_csrgather(const int* __restrict__ src, const int* __restrict__ dst,
                            const float* __restrict__ bond) {
    int i = blockIdx.x * blockDim.x + threadIdx.x;
    if (i >= N_EDGES) return;
    int e = d_csr_eid[i];
    d_csr_src[i] = src[e];
    d_csr_dst[i] = dst[e];
    d_csr_bond[i] = bond[e];
}

// ---------------- embed GEMM via HMMA: h = atomh[NPAD,96] @ wembh[96,64] + b ----------------
__global__ __launch_bounds__(256) void k_gemm_embh(const float* __restrict__ bias) {
    int m0 = blockIdx.x * 128;
    int wid = threadIdx.x >> 5;
    int lane = threadIdx.x & 31;
    int mw = wid & 3;
    int nw = wid >> 2;

    wmma::fragment<wmma::accumulator, 16, 16, 16, float> acc[2][2];
#pragma unroll
    for (int mi = 0; mi < 2; mi++)
#pragma unroll
        for (int nj = 0; nj < 2; nj++) wmma::fill_fragment(acc[mi][nj], 0.f);

#pragma unroll
    for (int kk = 0; kk < 6; kk++) {
        wmma::fragment<wmma::matrix_a, 16, 16, 16, __half, wmma::row_major> af[2];
        wmma::fragment<wmma::matrix_b, 16, 16, 16, __half, wmma::row_major> bf[2];
#pragma unroll
        for (int mi = 0; mi < 2; mi++)
            wmma::load_matrix_sync(af[mi], d_atomh + (m0 + mw * 32 + mi * 16) * AIFP + kk * 16, AIFP);
#pragma unroll
        for (int nj = 0; nj < 2; nj++)
            wmma::load_matrix_sync(bf[nj], d_wembh + (kk * 16) * 64 + nw * 32 + nj * 16, 64);
#pragma unroll
        for (int mi = 0; mi < 2; mi++)
#pragma unroll
            for (int nj = 0; nj < 2; nj++)
                wmma::mma_sync(acc[mi][nj], af[mi], bf[nj], acc[mi][nj]);
    }

    __shared__ float patch[8][256];
    float* p = patch[wid];
#pragma unroll
    for (int mi = 0; mi < 2; mi++)
#pragma unroll
        for (int nj = 0; nj < 2; nj++) {
            wmma::store_matrix_sync(p, acc[mi][nj], 16, wmma::mem_row_major);
            __syncwarp();
            int row0 = m0 + mw * 32 + mi * 16;
            int col0 = nw * 32 + nj * 16;
#pragma unroll
            for (int j = 0; j < 8; j++) {
                int q = lane + 32 * j;
                int r = q >> 4, c = q & 15;
                float v = p[r * 16 + c] + bias[col0 + c];
                int o = (row0 + r) * 64 + col0 + c;
                d_h[o] = v;
                d_hh[o] = __float2half(v);
            }
            __syncwarp();
        }
}

// ---------------- layer GEMM via HMMA: ABp = hh[NPAD,64] @ wbigh[l][64,256] ----------------
__global__ __launch_bounds__(256) void k_gemmAB(int layer) {
    const __half* A = d_hh;
    const __half* B = d_wbigh + layer * 64 * 256;
    int m0 = blockIdx.x * 64;
    int wid = threadIdx.x >> 5;
    int lane = threadIdx.x & 31;
    int mw = wid & 1;
    int nw = wid >> 1;

    wmma::fragment<wmma::accumulator, 16, 16, 16, float> acc[2][4];
#pragma unroll
    for (int mi = 0; mi < 2; mi++)
#pragma unroll
        for (int nj = 0; nj < 4; nj++) wmma::fill_fragment(acc[mi][nj], 0.f);

#pragma unroll
    for (int kk = 0; kk < 4; kk++) {
        wmma::fragment<wmma::matrix_a, 16, 16, 16, __half, wmma::row_major> af[2];
        wmma::fragment<wmma::matrix_b, 16, 16, 16, __half, wmma::row_major> bf[4];
#pragma unroll
        for (int mi = 0; mi < 2; mi++)
            wmma::load_matrix_sync(af[mi], A + (m0 + mw * 32 + mi * 16) * 64 + kk * 16, 64);
#pragma unroll
        for (int nj = 0; nj < 4; nj++)
            wmma::load_matrix_sync(bf[nj], B + (kk * 16) * 256 + nw * 64 + nj * 16, 256);
#pragma unroll
        for (int mi = 0; mi < 2; mi++)
#pragma unroll
            for (int nj = 0; nj < 4; nj++)
                wmma::mma_sync(acc[mi][nj], af[mi], bf[nj], acc[mi][nj]);
    }

    __shared__ float patch[8][256];
    float* p = patch[wid];
#pragma unroll
    for (int mi = 0; mi < 2; mi++)
#pragma unroll
        for (int nj = 0; nj < 4; nj++) {
            wmma::store_matrix_sync(p, acc[mi][nj], 16, wmma::mem_row_major);
            __syncwarp();
            int row0 = m0 + mw * 32 + mi * 16;
            int pairbase = nw * 32 + nj * 8;
#pragma unroll
            for (int j = 0; j < 4; j++) {
                int q = lane * 4 + j;
                int r = q >> 3, pp = q & 7;
                d_ABp[(row0 + r) * 128 + pairbase + pp] =
                    __floats2half2_rn(p[r * 16 + 2 * pp], p[r * 16 + 2 * pp + 1]);
            }
            __syncwarp();
        }
}

// ---------------- stats: fully edge-centric, 2-edge unroll, no stores ----------------
__global__ __launch_bounds__(256) void k_stats(int layer) {
    int tid = threadIdx.x;
    int f = tid & 63, g = tid >> 6;
    const __half2* Tb = d_tab + layer * TROWS * 64;
    float s1i = 0.f, s2i = 0.f, s1u = 0.f, s2u = 0.f;
    for (int i = blockIdx.x * 8 + g * 2; i < N_EDGES; i += gridDim.x * 8) {
        int snA = d_csr_src[i];
        int dnA = d_csr_dst[i];
        float blA = d_csr_bond[i];
        int tA = __float2int_rn(blA * ((float)TBINS / 8.0f));
        float2 aA = __half22float2(d_ABp[snA * 128 + f]);
        float2 bA = __half22float2(d_ABp[dnA * 128 + 64 + f]);
        float2 uA = __half22float2(Tb[tA * 64 + f]);
        float piA = aA.x + bA.x + uA.x, puA = aA.y + bA.y + uA.y;
        s1i += piA; s2i = fmaf(piA, piA, s2i);
        s1u += puA; s2u = fmaf(puA, puA, s2u);
        int j = i + 1;
        if (j < N_EDGES) {
            int snB = d_csr_src[j];
            int dnB = d_csr_dst[j];
            float blB = d_csr_bond[j];
            int tB = __float2int_rn(blB * ((float)TBINS / 8.0f));
            float2 aB = __half22float2(d_ABp[snB * 128 + f]);
            float2 bB = __half22float2(d_ABp[dnB * 128 + 64 + f]);
            float2 uB = __half22float2(Tb[tB * 64 + f]);
            float piB = aB.x + bB.x + uB.x, puB = aB.y + bB.y + uB.y;
            s1i += piB; s2i = fmaf(piB, piB, s2i);
            s1u += puB; s2u = fmaf(puB, puB, s2u);
        }
    }
    float* es = d_estat + layer * 256;
    __shared__ float red[256];
    red[tid] = s1i; __syncthreads();
    if (tid < 64) atomicAdd(&es[f], red[f] + red[f + 64] + red[f + 128] + red[f + 192]);
    __syncthreads(); red[tid] = s2i; __syncthreads();
    if (tid < 64) atomicAdd(&es[64 + f], red[f] + red[f + 64] + red[f + 128] + red[f + 192]);
    __syncthreads(); red[tid] = s1u; __syncthreads();
    if (tid < 64) atomicAdd(&es[128 + f], red[f] + red[f + 64] + red[f + 128] + red[f + 192]);
    __syncthreads(); red[tid] = s2u; __syncthreads();
    if (tid < 64) atomicAdd(&es[192 + f], red[f] + red[f + 64] + red[f + 128] + red[f + 192]);
}

// ---------------- apply: warp-per-node, 2-edge pipeline, fused edge-BN finalize ----------------
__global__ __launch_bounds__(256) void k_apply(const float* __restrict__ gi,
                                               const float* __restrict__ bti,
                                               const float* __restrict__ gu,
                                               const float* __restrict__ btu,
                                               int layer) {
    __shared__ float sci[64], shi[64], scu[64], shu[64];
    int tid = threadIdx.x;
    if (tid < 128) {
        const float* es = d_estat + layer * 256;
        int c = tid;
        if (c < 64) {
            float mean = es[c] * (1.f / N_EDGES);
            float var = es[64 + c] * (1.f / N_EDGES) - mean * mean;
            float s = gi[layer * 64 + c] * rsqrtf(var + BN_EPS);
            sci[c] = s; shi[c] = bti[layer * 64 + c] - mean * s;
        } else {
            int f = c - 64;
            float mean = es[128 + f] * (1.f / N_EDGES);
            float var = es[192 + f] * (1.f / N_EDGES) - mean * mean;
            float s = gu[layer * 64 + f] * rsqrtf(var + BN_EPS);
            scu[f] = s; shu[f] = btu[layer * 64 + f] - mean * s;
        }
    }
    __syncthreads();
    int wid = tid >> 5, lane = tid & 31;
    float ci0 = sci[lane], hi0 = shi[lane], cu0 = scu[lane], hu0 = shu[lane];
    float ci1 = sci[lane + 32], hi1 = shi[lane + 32], cu1 = scu[lane + 32], hu1 = shu[lane + 32];
    const __half2* Tb = d_tab + layer * TROWS * 64;
    float s10 = 0.f, s20 = 0.f, s11 = 0.f, s21 = 0.f;
    for (int n = blockIdx.x * 8 + wid; n < N_NODES; n += gridDim.x * 8) {
        int a0 = d_rowstart[n], a1 = d_rowstart[n + 1];
        float2 b0 = __half22float2(d_ABp[n * 128 + 64 + lane]);
        float2 b1 = __half22float2(d_ABp[n * 128 + 96 + lane]);
        float accA0 = 0.f, accA1 = 0.f, accB0 = 0.f, accB1 = 0.f;
        int i = a0;
        for (; i + 1 < a1; i += 2) {
            int snA = d_csr_src[i], snB = d_csr_src[i + 1];
            float blA = d_csr_bond[i], blB = d_csr_bond[i + 1];
            int tA = __float2int_rn(blA * ((float)TBINS / 8.0f));
            int tB = __float2int_rn(blB * ((float)TBINS / 8.0f));
            float2 aA0 = __half22float2(d_ABp[snA * 128 + lane]);
            float2 aA1 = __half22float2(d_ABp[snA * 128 + 32 + lane]);
            float2 aB0 = __half22float2(d_ABp[snB * 128 + lane]);
            float2 aB1 = __half22float2(d_ABp[snB * 128 + 32 + lane]);
            float2 uA0 = __half22float2(Tb[tA * 64 + lane]);
            float2 uA1 = __half22float2(Tb[tA * 64 + 32 + lane]);
            float2 uB0 = __half22float2(Tb[tB * 64 + lane]);
            float2 uB1 = __half22float2(Tb[tB * 64 + 32 + lane]);
            accA0 = fmaf(fsig(fmaf(aA0.x + b0.x + uA0.x, ci0, hi0)),
                         fsp(fmaf(aA0.y + b0.y + uA0.y, cu0, hu0)), accA0);
            accA1 = fmaf(fsig(fmaf(aA1.x + b1.x + uA1.x, ci1, hi1)),
                         fsp(fmaf(aA1.y + b1.y + uA1.y, cu1, hu1)), accA1);
            accB0 = fmaf(fsig(fmaf(aB0.x + b0.x + uB0.x, ci0, hi0)),
                         fsp(fmaf(aB0.y + b0.y + uB0.y, cu0, hu0)), accB0);
            accB1 = fmaf(fsig(fmaf(aB1.x + b1.x + uB1.x, ci1, hi1)),
                         fsp(fmaf(aB1.y + b1.y + uB1.y, cu1, hu1)), accB1);
        }
        if (i < a1) {
            int sn = d_csr_src[i];
            float bl = d_csr_bond[i];
            int t = __float2int_rn(bl * ((float)TBINS / 8.0f));
            float2 a0v = __half22float2(d_ABp[sn * 128 + lane]);
            float2 a1v = __half22float2(d_ABp[sn * 128 + 32 + lane]);
            float2 u0 = __half22float2(Tb[t * 64 + lane]);
            float2 u1 = __half22float2(Tb[t * 64 + 32 + lane]);
            accA0 = fmaf(fsig(fmaf(a0v.x + b0.x + u0.x, ci0, hi0)),
                         fsp(fmaf(a0v.y + b0.y + u0.y, cu0, hu0)), accA0);
            accA1 = fmaf(fsig(fmaf(a1v.x + b1.x + u1.x, ci1, hi1)),
                         fsp(fmaf(a1v.y + b1.y + u1.y, cu1, hu1)), accA1);
        }
        float v0 = accA0 + accB0, v1 = accA1 + accB1;
        d_agg[n * 64 + lane] = v0;
        d_agg[n * 64 + 32 + lane] = v1;
        s10 += v0; s20 = fmaf(v0, v0, s20);
        s11 += v1; s21 = fmaf(v1, v1, s21);
    }
    // node-BN stats reduce: ns[f]=s1, ns[64+f]=s2
    float* ns = d_nstat + layer * 128;
    __shared__ float red[256];
    red[tid] = s10; __syncthreads();
    if (tid < 32) { float a = 0; for (int w = 0; w < 8; w++) a += red[w * 32 + tid]; atomicAdd(&ns[tid], a); }
    __syncthreads(); red[tid] = s11; __syncthreads();
    if (tid < 32) { float a = 0; for (int w = 0; w < 8; w++) a += red[w * 32 + tid]; atomicAdd(&ns[32 + tid], a); }
    __syncthreads(); red[tid] = s20; __syncthreads();
    if (tid < 32) { float a = 0; for (int w = 0; w < 8; w++) a += red[w * 32 + tid]; atomicAdd(&ns[64 + tid], a); }
    __syncthreads(); red[tid] = s21; __syncthreads();
    if (tid < 32) { float a = 0; for (int w = 0; w < 8; w++) a += red[w * 32 + tid]; atomicAdd(&ns[96 + tid], a); }
}

// ---------------- N2 with fused node-BN finalize: h = softplus(h + bn(agg)) ----------------
__global__ __launch_bounds__(256) void k_N2(const float* __restrict__ g_bn,
                                            const float* __restrict__ b_bn, int layer) {
    __shared__ float sc[64], sh[64];
    int tid = threadIdx.x;
    if (tid < 64) {
        const float* ns = d_nstat + layer * 128;
        float mean = ns[tid] * (1.f / N_NODES);
        float var = ns[64 + tid] * (1.f / N_NODES) - mean * mean;
        float s = g_bn[layer * 64 + tid] * rsqrtf(var + BN_EPS);
        sc[tid] = s;
        sh[tid] = b_bn[layer * 64 + tid] - mean * s;
    }
    __syncthreads();
    int total = N_NODES * NF;
    for (int i = blockIdx.x * 256 + tid; i < total; i += gridDim.x * 256) {
        int f = i & 63;
        float a = fmaf(d_agg[i], sc[f], sh[f]);
        float v = fsp(d_h[i] + a);
        d_h[i] = v;
        d_hh[i] = __float2half(v);
    }
}

// ---------------- final: mean pool per graph + MLP head ----------------
__device__ __forceinline__ int lbound(const int* a, int n, int v) {
    int lo = 0, hi = n;
    while (lo < hi) {
        int mid = (lo + hi) >> 1;
        if (a[mid] < v) lo = mid + 1; else hi = mid;
    }
    return lo;
}

__global__ __launch_bounds__(128) void k_final(const int* __restrict__ gids,
                                               const float* __restrict__ Wfc,
                                               const float* __restrict__ bfc,
                                               const float* __restrict__ Wout,
                                               const float* __restrict__ bout,
                                               float* __restrict__ out) {
    int g = blockIdx.x;
    int tid = threadIdx.x;
    __shared__ int bounds[2];
    __shared__ float f1s[64];
    __shared__ float red[128];
    if (tid == 0) {
        bounds[0] = lbound(gids, N_NODES, g);
        bounds[1] = lbound(gids, N_NODES, g + 1);
    }
    __syncthreads();
    int lo = bounds[0], hi = bounds[1];
    int f = tid & 63, half = tid >> 6;
    float s = 0.f;
    for (int n = lo + half; n < hi; n += 2) s += d_h[n * 64 + f];
    red[tid] = s;
    __syncthreads();
    if (tid < 64) {
        float tot = red[tid] + red[tid + 64];
        float cnt = (float)max(hi - lo, 1);
        f1s[tid] = fsp(tot / cnt);
    }
    __syncthreads();
    float acc = bfc[tid];
#pragma unroll
    for (int k = 0; k < 64; k++) acc = fmaf(f1s[k], Wfc[k * FCF + tid], acc);
    float v = fsp(fsp(acc)) * Wout[tid];
    red[tid] = v;
    __syncthreads();
    for (int st = 64; st > 0; st >>= 1) {
        if (tid < st) red[tid] += red[tid + st];
        __syncthreads();
    }
    if (tid == 0) out[g] = red[0] + bout[0];
}

// ---------------- launch ----------------
extern "C" void kernel_launch(void* const* d_in, const int* in_sizes, int n_in,
                              void* d_out, int out_size) {
    const float* atom  = (const float*)d_in[0];
    const float* bond  = (const float*)d_in[1];
    const int*   src   = (const int*)d_in[2];
    const int*   dst   = (const int*)d_in[3];
    const int*   gids  = (const int*)d_in[4];
    const float* W_emb = (const float*)d_in[5];
    const float* b_emb = (const float*)d_in[6];
    const float* Wi    = (const float*)d_in[7];
    // d_in[8] = bi  — cancels inside training-mode BatchNorm
    const float* gi    = (const float*)d_in[9];
    const float* bti   = (const float*)d_in[10];
    const float* Wu    = (const float*)d_in[11];
    // d_in[12] = bu — cancels
    const float* gu    = (const float*)d_in[13];
    const float* btu   = (const float*)d_in[14];
    const float* g_bn  = (const float*)d_in[15];
    const float* b_bn  = (const float*)d_in[16];
    const float* W_fc  = (const float*)d_in[17];
    const float* b_fc  = (const float*)d_in[18];
    const float* W_out = (const float*)d_in[19];
    const float* b_out = (const float*)d_in[20];
    float* out = (float*)d_out;

    const int EB = (N_EDGES + 255) / 256;   // 1563
    const int NB = (N_NODES + 255) / 256;   // 196
    const int SB = (N_NODES + 511) / 512;   // 98

    k_wbig<<<48, 1024>>>(Wi, Wu);
    k_etab<<<(TROWS * EF + 255) / 256, 256>>>();
    k_table<<<NLAYERS * TBLK, 256>>>(Wi, Wu);
    k_convatom<<<NPAD / 2, dim3(96, 2)>>>(atom);
    k_convw<<<(AIFP * NF + 255) / 256, 256>>>(W_emb);
    k_count<<<EB, 256>>>(dst);
    k_scan1<<<SB, 512>>>();
    k_scan2<<<1, 128>>>(SB);
    k_scan3<<<SB, 512>>>();
    k_fill<<<EB, 256>>>(dst);
    k_sort<<<NB, 256>>>();
    k_csrgather<<<EB, 256>>>(src, dst, bond);

    k_gemm_embh<<<NPAD / 128, 256>>>(b_emb);

    for (int l = 0; l < NLAYERS; l++) {
        k_gemmAB<<<NPAD / 64, 256>>>(l);
        k_stats<<<1024, 256>>>(l);
        k_apply<<<6250, 256>>>(gi, bti, gu, btu, l);
        k_N2<<<2048, 256>>>(g_bn, b_bn, l);
    }

    k_final<<<N_GRAPHS, 128>>>(gids, W_fc, b_fc, W_out, b_out, out);
}

// round 6
// speedup vs baseline: 1.2604x; 1.0591x over previous
#include <cuda_runtime.h>
#include <cuda_fp16.h>
#include <mma.h>
#include <math.h>

using namespace nvcuda;

#define N_NODES 50000
#define NPAD 50048          // 782 * 64
#define N_EDGES 400000
#define N_GRAPHS 512
#define NF 64
#define EF 32
#define AIF 92
#define AIFP 96
#define FCF 128
#define NLAYERS 3
#define TBINS 16384
#define TROWS 16385
#define BN_EPS 1e-5f

// ---------------- static scratch ----------------
__device__ __align__(16) float   d_h[NPAD * NF];
__device__ __align__(16) __half  d_hh[NPAD * NF];
__device__ __align__(16) float   d_agg[NPAD * NF];
__device__ __align__(16) __half2 d_ABp[NPAD * 128];            // packed (i,u): [0..63]=A, [64..127]=B
__device__ __align__(16) __half2 d_tab[NLAYERS * TROWS * 64];  // RBF@W table (nearest bin)
__device__ __align__(16) __half  d_wbigh[NLAYERS * 64 * 256];
__device__ __align__(16) __half  d_atomh[NPAD * AIFP];
__device__ __align__(16) __half  d_wembh[AIFP * NF];
__device__ __align__(16) float   d_E[TROWS * EF];
__device__ int   d_counts[N_NODES];
__device__ int   d_rowstart[N_NODES + 1];
__device__ int   d_cursor[N_NODES];
__device__ int   d_bsum[128];
__device__ int   d_boff[128];
__device__ int   d_csr_eid[N_EDGES];
__device__ __align__(16) int4 d_e4[N_EDGES];   // (src, dst, tbin, 0)  for stats
__device__ __align__(8)  int2 d_e2[N_EDGES];   // (src, tbin)          for apply
__device__ float d_estat[NLAYERS * 256];
__device__ float d_nstat[NLAYERS * 128];

// ---------------- fast math ----------------
__device__ __forceinline__ float fsig(float x) {
    return __fdividef(1.f, 1.f + __expf(-x));
}
__device__ __forceinline__ float fsp(float x) {
    return fmaxf(x, 0.f) + __logf(1.f + __expf(-fabsf(x)));
}

// ---------------- prep: pack fp16 weights (interleaved), zero stat slabs ----------------
__global__ void k_wbig(const float* __restrict__ Wi, const float* __restrict__ Wu) {
    int tid = threadIdx.x;
    int idx = blockIdx.x * blockDim.x + tid;
    if (blockIdx.x == 0) {
        if (tid < NLAYERS * 256) d_estat[tid] = 0.f;
    } else if (blockIdx.x == 1) {
        if (tid < NLAYERS * 128) d_nstat[tid] = 0.f;
    }
    for (int i = idx; i < N_NODES; i += gridDim.x * blockDim.x) d_counts[i] = 0;
    if (idx >= NLAYERS * 64 * 256) return;
    int l = idx / 16384;
    int r = idx - l * 16384;
    int k = r >> 8;
    int c = r & 255;
    float v;
    if (c < 128) {
        int f = c >> 1;
        int base = (l * 160 + k) * 64 + f;
        v = (c & 1) ? Wu[base] : Wi[base];
    } else {
        int f = (c - 128) >> 1;
        int base = (l * 160 + 64 + k) * 64 + f;
        v = (c & 1) ? Wu[base] : Wi[base];
    }
    d_wbigh[idx] = __float2half(v);
}

// ---------------- RBF basis ----------------
__global__ void k_etab() {
    int idx = blockIdx.x * blockDim.x + threadIdx.x;
    if (idx >= TROWS * EF) return;
    int t = idx >> 5, k = idx & 31;
    float d = (float)t * (8.0f / (float)TBINS);
    float ck = (float)k * (8.0f / 31.0f);
    float diff = d - ck;
    d_E[idx] = expf(-3.875f * diff * diff);
}

// ---------------- table build ----------------
#define TCH 64
#define TBLK 257
__global__ __launch_bounds__(256) void k_table(const float* __restrict__ Wi,
                                               const float* __restrict__ Wu) {
    int b = blockIdx.x;
    int l = b / TBLK;
    int t0 = (b - l * TBLK) * TCH;
    int tid = threadIdx.x;
    __shared__ float ws[2][32 * 64];
    __shared__ float es[TCH * 32];
    for (int idx = tid; idx < 32 * 64; idx += 256) {
        int k = idx >> 6, f = idx & 63;
        ws[0][idx] = Wi[(l * 160 + 128 + k) * 64 + f];
        ws[1][idx] = Wu[(l * 160 + 128 + k) * 64 + f];
    }
    for (int idx = tid; idx < TCH * 32; idx += 256) {
        int tl = idx >> 5, k = idx & 31;
        int t = t0 + tl;
        es[idx] = (t < TROWS) ? d_E[t * 32 + k] : 0.f;
    }
    __syncthreads();
    for (int o = tid; o < TCH * 64; o += 256) {
        int tl = o >> 6, f = o & 63;
        int t = t0 + tl;
        if (t >= TROWS) continue;
        float ai = 0.f, au = 0.f;
#pragma unroll
        for (int k = 0; k < 32; k++) {
            float e = es[tl * 32 + k];
            ai = fmaf(e, ws[0][k * 64 + f], ai);
            au = fmaf(e, ws[1][k * 64 + f], au);
        }
        d_tab[(l * TROWS + t) * 64 + f] = __floats2half2_rn(ai, au);
    }
}

// ---------------- fp16 conversions (vectorized) ----------------
__global__ void k_convatom(const float* __restrict__ atom) {
    int idx = blockIdx.x * blockDim.x + threadIdx.x;   // over NPAD * 24
    if (idx >= NPAD * 24) return;
    int row = idx / 24, c4 = idx - row * 24;
    float4 v = make_float4(0.f, 0.f, 0.f, 0.f);
    if (row < N_NODES && c4 < 23) v = *(const float4*)&atom[row * AIF + c4 * 4];
    __half2* o = (__half2*)&d_atomh[row * AIFP + c4 * 4];
    o[0] = __floats2half2_rn(v.x, v.y);
    o[1] = __floats2half2_rn(v.z, v.w);
}

__global__ void k_convw(const float* __restrict__ W) {
    int idx = blockIdx.x * blockDim.x + threadIdx.x;
    if (idx >= AIFP * NF) return;
    int k = idx >> 6, c = idx & 63;
    d_wembh[idx] = __float2half(k < AIF ? W[k * 64 + c] : 0.f);
}

// ---------------- CSR build ----------------
__global__ void k_count(const int* __restrict__ dst) {
    int e = blockIdx.x * blockDim.x + threadIdx.x;
    if (e < N_EDGES) atomicAdd(&d_counts[dst[e]], 1);
}

__global__ void k_scan1() {
    int b = blockIdx.x, tid = threadIdx.x;
    int i = b * 512 + tid;
    int v = (i < N_NODES) ? d_counts[i] : 0;
    __shared__ int s[512];
    s[tid] = v;
    __syncthreads();
    for (int o = 1; o < 512; o <<= 1) {
        int t = (tid >= o) ? s[tid - o] : 0;
        __syncthreads();
        s[tid] += t;
        __syncthreads();
    }
    if (i < N_NODES) d_rowstart[i] = s[tid] - v;
    if (tid == 511) d_bsum[b] = s[511];
}

__global__ void k_scan2(int nblk) {
    int tid = threadIdx.x;
    int v = (tid < nblk) ? d_bsum[tid] : 0;
    __shared__ int s[128];
    s[tid] = v;
    __syncthreads();
    for (int o = 1; o < 128; o <<= 1) {
        int t = (tid >= o) ? s[tid - o] : 0;
        __syncthreads();
        s[tid] += t;
        __syncthreads();
    }
    d_boff[tid] = s[tid] - v;
}

__global__ void k_scan3() {
    int i = blockIdx.x * blockDim.x + threadIdx.x;
    if (i >= N_NODES) return;
    int rs = d_rowstart[i] + d_boff[i >> 9];
    d_rowstart[i] = rs;
    d_cursor[i] = rs;
    if (i == 0) d_rowstart[N_NODES] = N_EDGES;
}

__global__ void k_fill(const int* __restrict__ dst) {
    int e = blockIdx.x * blockDim.x + threadIdx.x;
    if (e >= N_EDGES) return;
    int pos = atomicAdd(&d_cursor[dst[e]], 1);
    d_csr_eid[pos] = e;
}

__global__ void k_sort() {
    int n = blockIdx.x * blockDim.x + threadIdx.x;
    if (n >= N_NODES) return;
    int s = d_rowstart[n], e = d_rowstart[n + 1];
    for (int i = s + 1; i < e; i++) {
        int v = d_csr_eid[i];
        int j = i - 1;
        while (j >= s && d_csr_eid[j] > v) {
            d_csr_eid[j + 1] = d_csr_eid[j];
            j--;
        }
        d_csr_eid[j + 1] = v;
    }
}

__global__ void k_csrgather(const int* __restrict__ src, const int* __restrict__ dst,
                            const float* __restrict__ bond) {
    int i = blockIdx.x * blockDim.x + threadIdx.x;
    if (i >= N_EDGES) return;
    int e = d_csr_eid[i];
    int s = src[e];
    int d = dst[e];
    int t = __float2int_rn(bond[e] * ((float)TBINS / 8.0f));
    d_e4[i] = make_int4(s, d, t, 0);
    d_e2[i] = make_int2(s, t);
}

// ---------------- embed GEMM via HMMA ----------------
__global__ __launch_bounds__(256) void k_gemm_embh(const float* __restrict__ bias) {
    int m0 = blockIdx.x * 128;
    int wid = threadIdx.x >> 5;
    int lane = threadIdx.x & 31;
    int mw = wid & 3;
    int nw = wid >> 2;

    wmma::fragment<wmma::accumulator, 16, 16, 16, float> acc[2][2];
#pragma unroll
    for (int mi = 0; mi < 2; mi++)
#pragma unroll
        for (int nj = 0; nj < 2; nj++) wmma::fill_fragment(acc[mi][nj], 0.f);

#pragma unroll
    for (int kk = 0; kk < 6; kk++) {
        wmma::fragment<wmma::matrix_a, 16, 16, 16, __half, wmma::row_major> af[2];
        wmma::fragment<wmma::matrix_b, 16, 16, 16, __half, wmma::row_major> bf[2];
#pragma unroll
        for (int mi = 0; mi < 2; mi++)
            wmma::load_matrix_sync(af[mi], d_atomh + (m0 + mw * 32 + mi * 16) * AIFP + kk * 16, AIFP);
#pragma unroll
        for (int nj = 0; nj < 2; nj++)
            wmma::load_matrix_sync(bf[nj], d_wembh + (kk * 16) * 64 + nw * 32 + nj * 16, 64);
#pragma unroll
        for (int mi = 0; mi < 2; mi++)
#pragma unroll
            for (int nj = 0; nj < 2; nj++)
                wmma::mma_sync(acc[mi][nj], af[mi], bf[nj], acc[mi][nj]);
    }

    __shared__ float patch[8][256];
    float* p = patch[wid];
#pragma unroll
    for (int mi = 0; mi < 2; mi++)
#pragma unroll
        for (int nj = 0; nj < 2; nj++) {
            wmma::store_matrix_sync(p, acc[mi][nj], 16, wmma::mem_row_major);
            __syncwarp();
            int row0 = m0 + mw * 32 + mi * 16;
            int col0 = nw * 32 + nj * 16;
#pragma unroll
            for (int j = 0; j < 8; j++) {
                int q = lane + 32 * j;
                int r = q >> 4, c = q & 15;
                float v = p[r * 16 + c] + bias[col0 + c];
                int o = (row0 + r) * 64 + col0 + c;
                d_h[o] = v;
                d_hh[o] = __float2half(v);
            }
            __syncwarp();
        }
}

// ---------------- layer GEMM via HMMA ----------------
__global__ __launch_bounds__(256) void k_gemmAB(int layer) {
    const __half* A = d_hh;
    const __half* B = d_wbigh + layer * 64 * 256;
    int m0 = blockIdx.x * 64;
    int wid = threadIdx.x >> 5;
    int lane = threadIdx.x & 31;
    int mw = wid & 1;
    int nw = wid >> 1;

    wmma::fragment<wmma::accumulator, 16, 16, 16, float> acc[2][4];
#pragma unroll
    for (int mi = 0; mi < 2; mi++)
#pragma unroll
        for (int nj = 0; nj < 4; nj++) wmma::fill_fragment(acc[mi][nj], 0.f);

#pragma unroll
    for (int kk = 0; kk < 4; kk++) {
        wmma::fragment<wmma::matrix_a, 16, 16, 16, __half, wmma::row_major> af[2];
        wmma::fragment<wmma::matrix_b, 16, 16, 16, __half, wmma::row_major> bf[4];
#pragma unroll
        for (int mi = 0; mi < 2; mi++)
            wmma::load_matrix_sync(af[mi], A + (m0 + mw * 32 + mi * 16) * 64 + kk * 16, 64);
#pragma unroll
        for (int nj = 0; nj < 4; nj++)
            wmma::load_matrix_sync(bf[nj], B + (kk * 16) * 256 + nw * 64 + nj * 16, 256);
#pragma unroll
        for (int mi = 0; mi < 2; mi++)
#pragma unroll
            for (int nj = 0; nj < 4; nj++)
                wmma::mma_sync(acc[mi][nj], af[mi], bf[nj], acc[mi][nj]);
    }

    __shared__ float patch[8][256];
    float* p = patch[wid];
#pragma unroll
    for (int mi = 0; mi < 2; mi++)
#pragma unroll
        for (int nj = 0; nj < 4; nj++) {
            wmma::store_matrix_sync(p, acc[mi][nj], 16, wmma::mem_row_major);
            __syncwarp();
            int row0 = m0 + mw * 32 + mi * 16;
            int pairbase = nw * 32 + nj * 8;
#pragma unroll
            for (int j = 0; j < 4; j++) {
                int q = lane * 4 + j;
                int r = q >> 3, pp = q & 7;
                d_ABp[(row0 + r) * 128 + pairbase + pp] =
                    __floats2half2_rn(p[r * 16 + 2 * pp], p[r * 16 + 2 * pp + 1]);
            }
            __syncwarp();
        }
}

// ---------------- stats: edge-centric, 4-edge batched loads ----------------
__global__ __launch_bounds__(256) void k_stats(int layer) {
    int tid = threadIdx.x;
    int f = tid & 63, g = tid >> 6;
    const __half2* Tb = d_tab + layer * TROWS * 64;
    float s1i = 0.f, s2i = 0.f, s1u = 0.f, s2u = 0.f;
    for (int base = blockIdx.x * 16 + g * 4; base < N_EDGES; base += gridDim.x * 16) {
        int4 e[4];
        float2 av[4], bv[4], uv[4];
        float m[4];
#pragma unroll
        for (int j = 0; j < 4; j++) {
            int ii = base + j;
            m[j] = (ii < N_EDGES) ? 1.f : 0.f;
            e[j] = d_e4[min(ii, N_EDGES - 1)];
        }
#pragma unroll
        for (int j = 0; j < 4; j++) {
            av[j] = __half22float2(d_ABp[e[j].x * 128 + f]);
            bv[j] = __half22float2(d_ABp[e[j].y * 128 + 64 + f]);
            uv[j] = __half22float2(Tb[e[j].z * 64 + f]);
        }
#pragma unroll
        for (int j = 0; j < 4; j++) {
            float pi = av[j].x + bv[j].x + uv[j].x;
            float pu = av[j].y + bv[j].y + uv[j].y;
            float pim = pi * m[j], pum = pu * m[j];
            s1i += pim; s2i = fmaf(pim, pi, s2i);
            s1u += pum; s2u = fmaf(pum, pu, s2u);
        }
    }
    float* es = d_estat + layer * 256;
    __shared__ float red[256];
    red[tid] = s1i; __syncthreads();
    if (tid < 64) atomicAdd(&es[f], red[f] + red[f + 64] + red[f + 128] + red[f + 192]);
    __syncthreads(); red[tid] = s2i; __syncthreads();
    if (tid < 64) atomicAdd(&es[64 + f], red[f] + red[f + 64] + red[f + 128] + red[f + 192]);
    __syncthreads(); red[tid] = s1u; __syncthreads();
    if (tid < 64) atomicAdd(&es[128 + f], red[f] + red[f + 64] + red[f + 128] + red[f + 192]);
    __syncthreads(); red[tid] = s2u; __syncthreads();
    if (tid < 64) atomicAdd(&es[192 + f], red[f] + red[f + 64] + red[f + 128] + red[f + 192]);
}

// ---------------- apply: warp-per-node, 4-edge batched loads, fused edge-BN ----------------
__global__ __launch_bounds__(256) void k_apply(const float* __restrict__ gi,
                                               const float* __restrict__ bti,
                                               const float* __restrict__ gu,
                                               const float* __restrict__ btu,
                                               int layer) {
    __shared__ float sci[64], shi[64], scu[64], shu[64];
    int tid = threadIdx.x;
    if (tid < 128) {
        const float* es = d_estat + layer * 256;
        int c = tid;
        if (c < 64) {
            float mean = es[c] * (1.f / N_EDGES);
            float var = es[64 + c] * (1.f / N_EDGES) - mean * mean;
            float s = gi[layer * 64 + c] * rsqrtf(var + BN_EPS);
            sci[c] = s; shi[c] = bti[layer * 64 + c] - mean * s;
        } else {
            int f = c - 64;
            float mean = es[128 + f] * (1.f / N_EDGES);
            float var = es[192 + f] * (1.f / N_EDGES) - mean * mean;
            float s = gu[layer * 64 + f] * rsqrtf(var + BN_EPS);
            scu[f] = s; shu[f] = btu[layer * 64 + f] - mean * s;
        }
    }
    __syncthreads();
    int wid = tid >> 5, lane = tid & 31;
    float ci0 = sci[lane], hi0 = shi[lane], cu0 = scu[lane], hu0 = shu[lane];
    float ci1 = sci[lane + 32], hi1 = shi[lane + 32], cu1 = scu[lane + 32], hu1 = shu[lane + 32];
    const __half2* Tb = d_tab + layer * TROWS * 64;
    float s10 = 0.f, s20 = 0.f, s11 = 0.f, s21 = 0.f;
    for (int n = blockIdx.x * 8 + wid; n < N_NODES; n += gridDim.x * 8) {
        int a0 = d_rowstart[n], a1 = d_rowstart[n + 1];
        float2 b0 = __half22float2(d_ABp[n * 128 + 64 + lane]);
        float2 b1 = __half22float2(d_ABp[n * 128 + 96 + lane]);
        float acc0 = 0.f, acc1 = 0.f;
        int i = a0;
        for (; i + 4 <= a1; i += 4) {
            int2 e[4];
            float2 a0v[4], a1v[4], u0v[4], u1v[4];
#pragma unroll
            for (int j = 0; j < 4; j++) e[j] = d_e2[i + j];
#pragma unroll
            for (int j = 0; j < 4; j++) {
                a0v[j] = __half22float2(d_ABp[e[j].x * 128 + lane]);
                a1v[j] = __half22float2(d_ABp[e[j].x * 128 + 32 + lane]);
                u0v[j] = __half22float2(Tb[e[j].y * 64 + lane]);
                u1v[j] = __half22float2(Tb[e[j].y * 64 + 32 + lane]);
            }
#pragma unroll
            for (int j = 0; j < 4; j++) {
                acc0 = fmaf(fsig(fmaf(a0v[j].x + b0.x + u0v[j].x, ci0, hi0)),
                            fsp(fmaf(a0v[j].y + b0.y + u0v[j].y, cu0, hu0)), acc0);
                acc1 = fmaf(fsig(fmaf(a1v[j].x + b1.x + u1v[j].x, ci1, hi1)),
                            fsp(fmaf(a1v[j].y + b1.y + u1v[j].y, cu1, hu1)), acc1);
            }
        }
        for (; i < a1; i++) {
            int2 e = d_e2[i];
            float2 a0v = __half22float2(d_ABp[e.x * 128 + lane]);
            float2 a1v = __half22float2(d_ABp[e.x * 128 + 32 + lane]);
            float2 u0 = __half22float2(Tb[e.y * 64 + lane]);
            float2 u1 = __half22float2(Tb[e.y * 64 + 32 + lane]);
            acc0 = fmaf(fsig(fmaf(a0v.x + b0.x + u0.x, ci0, hi0)),
                        fsp(fmaf(a0v.y + b0.y + u0.y, cu0, hu0)), acc0);
            acc1 = fmaf(fsig(fmaf(a1v.x + b1.x + u1.x, ci1, hi1)),
                        fsp(fmaf(a1v.y + b1.y + u1.y, cu1, hu1)), acc1);
        }
        d_agg[n * 64 + lane] = acc0;
        d_agg[n * 64 + 32 + lane] = acc1;
        s10 += acc0; s20 = fmaf(acc0, acc0, s20);
        s11 += acc1; s21 = fmaf(acc1, acc1, s21);
    }
    float* ns = d_nstat + layer * 128;
    __shared__ float red[256];
    red[tid] = s10; __syncthreads();
    if (tid < 32) { float a = 0; for (int w = 0; w < 8; w++) a += red[w * 32 + tid]; atomicAdd(&ns[tid], a); }
    __syncthreads(); red[tid] = s11; __syncthreads();
    if (tid < 32) { float a = 0; for (int w = 0; w < 8; w++) a += red[w * 32 + tid]; atomicAdd(&ns[32 + tid], a); }
    __syncthreads(); red[tid] = s20; __syncthreads();
    if (tid < 32) { float a = 0; for (int w = 0; w < 8; w++) a += red[w * 32 + tid]; atomicAdd(&ns[64 + tid], a); }
    __syncthreads(); red[tid] = s21; __syncthreads();
    if (tid < 32) { float a = 0; for (int w = 0; w < 8; w++) a += red[w * 32 + tid]; atomicAdd(&ns[96 + tid], a); }
}

// ---------------- N2 (float2 vectorized): h = softplus(h + bn(agg)) ----------------
__global__ __launch_bounds__(256) void k_N2(const float* __restrict__ g_bn,
                                            const float* __restrict__ b_bn, int layer) {
    __shared__ float sc[64], sh[64];
    int tid = threadIdx.x;
    if (tid < 64) {
        const float* ns = d_nstat + layer * 128;
        float mean = ns[tid] * (1.f / N_NODES);
        float var = ns[64 + tid] * (1.f / N_NODES) - mean * mean;
        float s = g_bn[layer * 64 + tid] * rsqrtf(var + BN_EPS);
        sc[tid] = s;
        sh[tid] = b_bn[layer * 64 + tid] - mean * s;
    }
    __syncthreads();
    int total2 = N_NODES * NF / 2;
    for (int i = blockIdx.x * 256 + tid; i < total2; i += gridDim.x * 256) {
        int f2 = (i & 31) * 2;
        float2 a = *(const float2*)&d_agg[i * 2];
        float2 hv = *(const float2*)&d_h[i * 2];
        float v0 = fsp(hv.x + fmaf(a.x, sc[f2], sh[f2]));
        float v1 = fsp(hv.y + fmaf(a.y, sc[f2 + 1], sh[f2 + 1]));
        *(float2*)&d_h[i * 2] = make_float2(v0, v1);
        *(__half2*)&d_hh[i * 2] = __floats2half2_rn(v0, v1);
    }
}

// ---------------- final: mean pool per graph + MLP head ----------------
__device__ __forceinline__ int lbound(const int* a, int n, int v) {
    int lo = 0, hi = n;
    while (lo < hi) {
        int mid = (lo + hi) >> 1;
        if (a[mid] < v) lo = mid + 1; else hi = mid;
    }
    return lo;
}

__global__ __launch_bounds__(128) void k_final(const int* __restrict__ gids,
                                               const float* __restrict__ Wfc,
                                               const float* __restrict__ bfc,
                                               const float* __restrict__ Wout,
                                               const float* __restrict__ bout,
                                               float* __restrict__ out) {
    int g = blockIdx.x;
    int tid = threadIdx.x;
    __shared__ int bounds[2];
    __shared__ float f1s[64];
    __shared__ float red[128];
    if (tid == 0) {
        bounds[0] = lbound(gids, N_NODES, g);
        bounds[1] = lbound(gids, N_NODES, g + 1);
    }
    __syncthreads();
    int lo = bounds[0], hi = bounds[1];
    int f = tid & 63, half = tid >> 6;
    float s = 0.f;
    for (int n = lo + half; n < hi; n += 2) s += d_h[n * 64 + f];
    red[tid] = s;
    __syncthreads();
    if (tid < 64) {
        float tot = red[tid] + red[tid + 64];
        float cnt = (float)max(hi - lo, 1);
        f1s[tid] = fsp(tot / cnt);
    }
    __syncthreads();
    float acc = bfc[tid];
#pragma unroll
    for (int k = 0; k < 64; k++) acc = fmaf(f1s[k], Wfc[k * FCF + tid], acc);
    float v = fsp(fsp(acc)) * Wout[tid];
    red[tid] = v;
    __syncthreads();
    for (int st = 64; st > 0; st >>= 1) {
        if (tid < st) red[tid] += red[tid + st];
        __syncthreads();
    }
    if (tid == 0) out[g] = red[0] + bout[0];
}

// ---------------- launch ----------------
extern "C" void kernel_launch(void* const* d_in, const int* in_sizes, int n_in,
                              void* d_out, int out_size) {
    const float* atom  = (const float*)d_in[0];
    const float* bond  = (const float*)d_in[1];
    const int*   src   = (const int*)d_in[2];
    const int*   dst   = (const int*)d_in[3];
    const int*   gids  = (const int*)d_in[4];
    const float* W_emb = (const float*)d_in[5];
    const float* b_emb = (const float*)d_in[6];
    const float* Wi    = (const float*)d_in[7];
    // d_in[8] = bi  — cancels inside training-mode BatchNorm
    const float* gi    = (const float*)d_in[9];
    const float* bti   = (const float*)d_in[10];
    const float* Wu    = (const float*)d_in[11];
    // d_in[12] = bu — cancels
    const float* gu    = (const float*)d_in[13];
    const float* btu   = (const float*)d_in[14];
    const float* g_bn  = (const float*)d_in[15];
    const float* b_bn  = (const float*)d_in[16];
    const float* W_fc  = (const float*)d_in[17];
    const float* b_fc  = (const float*)d_in[18];
    const float* W_out = (const float*)d_in[19];
    const float* b_out = (const float*)d_in[20];
    float* out = (float*)d_out;

    const int EB = (N_EDGES + 255) / 256;
    const int NB = (N_NODES + 255) / 256;
    const int SB = (N_NODES + 511) / 512;

    k_wbig<<<48, 1024>>>(Wi, Wu);
    k_etab<<<(TROWS * EF + 255) / 256, 256>>>();
    k_table<<<NLAYERS * TBLK, 256>>>(Wi, Wu);
    k_convatom<<<(NPAD * 24 + 255) / 256, 256>>>(atom);
    k_convw<<<(AIFP * NF + 255) / 256, 256>>>(W_emb);
    k_count<<<EB, 256>>>(dst);
    k_scan1<<<SB, 512>>>();
    k_scan2<<<1, 128>>>(SB);
    k_scan3<<<SB, 512>>>();
    k_fill<<<EB, 256>>>(dst);
    k_sort<<<NB, 256>>>();
    k_csrgather<<<EB, 256>>>(src, dst, bond);

    k_gemm_embh<<<NPAD / 128, 256>>>(b_emb);

    for (int l = 0; l < NLAYERS; l++) {
        k_gemmAB<<<NPAD / 64, 256>>>(l);
        k_stats<<<2048, 256>>>(l);
        k_apply<<<6250, 256>>>(gi, bti, gu, btu, l);
        k_N2<<<2048, 256>>>(g_bn, b_bn, l);
    }

    k_final<<<N_GRAPHS, 128>>>(gids, W_fc, b_fc, W_out, b_out, out);
}